// round 4
// baseline (speedup 1.0000x reference)
#include <cuda_runtime.h>

// RNN2Classifier: B=4M, T=4, D=2, H=2 Elman cell + Linear(2->1).
// 4 batch elements per thread: 8x LDG.128 front-batched (128B/thread
// contiguous), 4 independent tanh chains (ILP-4), one STG.128.

__device__ __forceinline__ float htanh(float x) {
    float y;
    asm("tanh.approx.f32 %0, %1;" : "=f"(y) : "f"(x));
    return y;
}

struct Params {
    float w00, w01, w10, w11;
    float u00, u01, u10, u11;
    float bs0, bs1;
    float c0, c1, cbias;
};

__device__ __forceinline__ float rnn_one(const float4& xa, const float4& xb,
                                         const Params& p) {
    float x0[4] = {xa.x, xa.z, xb.x, xb.z};
    float x1[4] = {xa.y, xa.w, xb.y, xb.w};

    float h0 = htanh(fmaf(p.w00, x0[0], fmaf(p.w01, x1[0], p.bs0)));
    float h1 = htanh(fmaf(p.w10, x0[0], fmaf(p.w11, x1[0], p.bs1)));

    #pragma unroll
    for (int t = 1; t < 4; ++t) {
        float n0 = htanh(fmaf(p.u00, h0, fmaf(p.u01, h1,
                        fmaf(p.w00, x0[t], fmaf(p.w01, x1[t], p.bs0)))));
        float n1 = htanh(fmaf(p.u10, h0, fmaf(p.u11, h1,
                        fmaf(p.w10, x0[t], fmaf(p.w11, x1[t], p.bs1)))));
        h0 = n0;
        h1 = n1;
    }
    return fmaf(p.c0, h0, fmaf(p.c1, h1, p.cbias));
}

__global__ void __launch_bounds__(256) rnn2_kernel(
    const float4* __restrict__ X,     // [B,4,2] f32 = [B,2] float4
    const float*  __restrict__ wih,
    const float*  __restrict__ bih,
    const float*  __restrict__ whh,
    const float*  __restrict__ bhh,
    const float*  __restrict__ cw,
    const float*  __restrict__ cb,
    float* __restrict__ out,          // [B]
    int B)
{
    int i = blockIdx.x * blockDim.x + threadIdx.x;
    int b0 = i * 4;

    Params p;
    p.w00 = wih[0]; p.w01 = wih[1]; p.w10 = wih[2]; p.w11 = wih[3];
    p.u00 = whh[0]; p.u01 = whh[1]; p.u10 = whh[2]; p.u11 = whh[3];
    p.bs0 = bih[0] + bhh[0];
    p.bs1 = bih[1] + bhh[1];
    p.c0 = cw[0]; p.c1 = cw[1]; p.cbias = cb[0];

    if (b0 + 3 < B) {
        // 8 front-batched 16B loads: 128B contiguous per thread.
        const float4* Xi = X + 2 * b0;
        float4 v0 = Xi[0], v1 = Xi[1], v2 = Xi[2], v3 = Xi[3];
        float4 v4 = Xi[4], v5 = Xi[5], v6 = Xi[6], v7 = Xi[7];

        float4 r;
        r.x = rnn_one(v0, v1, p);
        r.y = rnn_one(v2, v3, p);
        r.z = rnn_one(v4, v5, p);
        r.w = rnn_one(v6, v7, p);

        *reinterpret_cast<float4*>(out + b0) = r;
    } else {
        // Scalar tail (B not divisible by 4).
        for (int b = b0; b < B; ++b) {
            float4 xa = X[2 * b], xb = X[2 * b + 1];
            out[b] = rnn_one(xa, xb, p);
        }
    }
}

extern "C" void kernel_launch(void* const* d_in, const int* in_sizes, int n_in,
                              void* d_out, int out_size)
{
    const float4* X   = (const float4*)d_in[0];
    const float*  wih = (const float*)d_in[1];
    const float*  bih = (const float*)d_in[2];
    const float*  whh = (const float*)d_in[3];
    const float*  bhh = (const float*)d_in[4];
    const float*  cw  = (const float*)d_in[5];
    const float*  cb  = (const float*)d_in[6];
    float* out = (float*)d_out;

    int B = in_sizes[0] / 8;           // X has B*4*2 floats
    int groups = (B + 3) / 4;          // 4 elements per thread
    int threads = 256;
    int blocks = (groups + threads - 1) / threads;
    rnn2_kernel<<<blocks, threads>>>(X, wih, bih, whh, bhh, cw, cb, out, B);
}

// round 5
// speedup vs baseline: 1.3868x; 1.3868x over previous
#include <cuda_runtime.h>

// RNN2Classifier: B=4M, T=4, D=2, H=2 Elman cell + Linear(2->1).
// 2 batch elements per thread. Loads forced front-batched via ordered
// volatile asm (4x LDG.128 = 64B/thread in flight), 2 independent tanh
// chains (ILP-2), one STG.64 per thread.

__device__ __forceinline__ float htanh(float x) {
    float y;
    asm("tanh.approx.f32 %0, %1;" : "=f"(y) : "f"(x));
    return y;
}

// Ordered 16B load: volatile asm keeps all loads ahead of compute in SASS.
__device__ __forceinline__ float4 ldg128(const float4* p) {
    float4 v;
    asm volatile("ld.global.nc.v4.f32 {%0,%1,%2,%3}, [%4];"
                 : "=f"(v.x), "=f"(v.y), "=f"(v.z), "=f"(v.w)
                 : "l"(p));
    return v;
}

struct Params {
    float w00, w01, w10, w11;
    float u00, u01, u10, u11;
    float bs0, bs1;
    float c0, c1, cbias;
};

__device__ __forceinline__ float rnn_one(const float4& xa, const float4& xb,
                                         const Params& p) {
    float x0[4] = {xa.x, xa.z, xb.x, xb.z};
    float x1[4] = {xa.y, xa.w, xb.y, xb.w};

    float h0 = htanh(fmaf(p.w00, x0[0], fmaf(p.w01, x1[0], p.bs0)));
    float h1 = htanh(fmaf(p.w10, x0[0], fmaf(p.w11, x1[0], p.bs1)));

    #pragma unroll
    for (int t = 1; t < 4; ++t) {
        float n0 = htanh(fmaf(p.u00, h0, fmaf(p.u01, h1,
                        fmaf(p.w00, x0[t], fmaf(p.w01, x1[t], p.bs0)))));
        float n1 = htanh(fmaf(p.u10, h0, fmaf(p.u11, h1,
                        fmaf(p.w10, x0[t], fmaf(p.w11, x1[t], p.bs1)))));
        h0 = n0;
        h1 = n1;
    }
    return fmaf(p.c0, h0, fmaf(p.c1, h1, p.cbias));
}

__global__ void __launch_bounds__(256) rnn2_kernel(
    const float4* __restrict__ X,     // [B,4,2] f32 = [B,2] float4
    const float*  __restrict__ wih,
    const float*  __restrict__ bih,
    const float*  __restrict__ whh,
    const float*  __restrict__ bhh,
    const float*  __restrict__ cw,
    const float*  __restrict__ cb,
    float* __restrict__ out,          // [B]
    int B)
{
    int i = blockIdx.x * blockDim.x + threadIdx.x;
    int b0 = i * 2;

    Params p;
    p.w00 = wih[0]; p.w01 = wih[1]; p.w10 = wih[2]; p.w11 = wih[3];
    p.u00 = whh[0]; p.u01 = whh[1]; p.u10 = whh[2]; p.u11 = whh[3];
    p.bs0 = bih[0] + bhh[0];
    p.bs1 = bih[1] + bhh[1];
    p.c0 = cw[0]; p.c1 = cw[1]; p.cbias = cb[0];

    if (b0 + 1 < B) {
        const float4* Xi = X + 2 * b0;
        // Four ordered 16B loads: all in flight before any compute.
        float4 v0 = ldg128(Xi + 0);
        float4 v1 = ldg128(Xi + 1);
        float4 v2 = ldg128(Xi + 2);
        float4 v3 = ldg128(Xi + 3);

        float2 r;
        r.x = rnn_one(v0, v1, p);
        r.y = rnn_one(v2, v3, p);

        *reinterpret_cast<float2*>(out + b0) = r;
    } else if (b0 < B) {
        float4 xa = X[2 * b0], xb = X[2 * b0 + 1];
        out[b0] = rnn_one(xa, xb, p);
    }
}

extern "C" void kernel_launch(void* const* d_in, const int* in_sizes, int n_in,
                              void* d_out, int out_size)
{
    const float4* X   = (const float4*)d_in[0];
    const float*  wih = (const float*)d_in[1];
    const float*  bih = (const float*)d_in[2];
    const float*  whh = (const float*)d_in[3];
    const float*  bhh = (const float*)d_in[4];
    const float*  cw  = (const float*)d_in[5];
    const float*  cb  = (const float*)d_in[6];
    float* out = (float*)d_out;

    int B = in_sizes[0] / 8;           // X has B*4*2 floats
    int groups = (B + 1) / 2;          // 2 elements per thread
    int threads = 256;
    int blocks = (groups + threads - 1) / threads;
    rnn2_kernel<<<blocks, threads>>>(X, wih, bih, whh, bhh, cw, cb, out, B);
}